// round 1
// baseline (speedup 1.0000x reference)
#include <cuda_runtime.h>
#include <cstdint>

// Problem constants
#define NGROUP 16
#define CPG    8            // channels per group (both in and out)
#define C      128          // total channels (in and out)
#define HW     (512 * 512)  // pixels per (batch, channel) plane
#define BATCH  4
#define PX_TILE 256         // pixels per CTA
#define THREADS 512         // 16 warps: one output group per warp

typedef unsigned long long u64;

// Transposed, weights: g_Wt[k * C + co] = weight[co * C + k]
__device__ float g_Wt[C * C];

__global__ void transpose_w_kernel(const float* __restrict__ w) {
    int co = blockIdx.x;   // 0..127
    int k  = threadIdx.x;  // 0..127
    g_Wt[k * C + co] = w[co * C + k];
}

// warp -> output-group permutation balancing triangular k-work across SMSPs.
// SMSP s gets warps {s, s+4, s+8, s+12}; (group+1) sums are 34 for every SMSP.
__constant__ int c_perm[16] = {15, 14, 11, 10,
                               12, 13,  8,  9,
                                3,  2,  7,  6,
                                0,  1,  4,  5};

// ---- packed f32x2 helpers (Blackwell sm_100+) ----
__device__ __forceinline__ u64 pack2(float v) {
    u64 r;
    unsigned u = __float_as_uint(v);
    asm("mov.b64 %0, {%1, %1};" : "=l"(r) : "r"(u));
    return r;
}
__device__ __forceinline__ void fma2(u64& d, u64 a, u64 b) {
    asm("fma.rn.f32x2 %0, %1, %2, %0;" : "+l"(d) : "l"(a), "l"(b));
}
__device__ __forceinline__ u64 add2(u64 a, u64 b) {
    u64 r;
    asm("add.rn.f32x2 %0, %1, %2;" : "=l"(r) : "l"(a), "l"(b));
    return r;
}

__global__ void __launch_bounds__(THREADS, 1)
cgconv_kernel(const float* __restrict__ x,
              const float* __restrict__ bias,
              float* __restrict__ out)
{
    // Tile mapping: PX_TILE contiguous pixels within one batch image.
    const int tiles_per_b = HW / PX_TILE;   // 1024
    int tile  = blockIdx.x;                 // 0 .. BATCH*tiles_per_b-1
    int b     = tile / tiles_per_b;
    int t_in  = tile - b * tiles_per_b;
    size_t base = (size_t)b * C * HW + (size_t)t_in * PX_TILE;

    int wid  = threadIdx.x >> 5;
    int lane = threadIdx.x & 31;

    int co_t = c_perm[wid];            // output group for this warp
    int kmax = (co_t + 1) * CPG;       // triangular bound: groups 0..co_t
    int co0  = co_t * CPG;

    // Per-thread pixel range: 8 consecutive pixels = 4 f32x2 pairs.
    const float* xrow = x + base + (size_t)lane * 8;

    // Weight row pointer: g_Wt[k*128 + co0 .. co0+7] = 2 float4 (uniform per warp)
    const float4* wt4 = reinterpret_cast<const float4*>(g_Wt);
    int wt_off = 2 * co_t;             // float4 index within a k-row (32 float4 per row)

    u64 acc[8][4];
#pragma unroll
    for (int j = 0; j < 8; ++j)
#pragma unroll
        for (int q = 0; q < 4; ++q) acc[j][q] = 0ull;

#pragma unroll 4
    for (int k = 0; k < kmax; ++k) {
        // X: 8 pixels = 2x LDG.128 (as ulonglong2)
        const ulonglong2* xr =
            reinterpret_cast<const ulonglong2*>(xrow + (size_t)k * HW);
        ulonglong2 xv0 = xr[0];
        ulonglong2 xv1 = xr[1];

        // W: 8 weights for this k, broadcast across the warp
        float4 wa = wt4[k * (C / 4) + wt_off];
        float4 wb = wt4[k * (C / 4) + wt_off + 1];
        u64 w[8] = { pack2(wa.x), pack2(wa.y), pack2(wa.z), pack2(wa.w),
                     pack2(wb.x), pack2(wb.y), pack2(wb.z), pack2(wb.w) };

#pragma unroll
        for (int j = 0; j < 8; ++j) {
            fma2(acc[j][0], w[j], xv0.x);
            fma2(acc[j][1], w[j], xv0.y);
            fma2(acc[j][2], w[j], xv1.x);
            fma2(acc[j][3], w[j], xv1.y);
        }
    }

    // Epilogue: add bias, store 8 pixels per output channel (2x STG.128)
#pragma unroll
    for (int j = 0; j < 8; ++j) {
        u64 bj = pack2(bias[co0 + j]);
        ulonglong2 v0, v1;
        v0.x = add2(acc[j][0], bj);
        v0.y = add2(acc[j][1], bj);
        v1.x = add2(acc[j][2], bj);
        v1.y = add2(acc[j][3], bj);
        float* orow = out + base + (size_t)(co0 + j) * HW + (size_t)lane * 8;
        reinterpret_cast<ulonglong2*>(orow)[0] = v0;
        reinterpret_cast<ulonglong2*>(orow)[1] = v1;
    }
}

extern "C" void kernel_launch(void* const* d_in, const int* in_sizes, int n_in,
                              void* d_out, int out_size)
{
    const float* x    = (const float*)d_in[0];
    const float* w    = (const float*)d_in[1];
    const float* bias = (const float*)d_in[2];
    float* out        = (float*)d_out;

    // 1) Transpose weights into g_Wt[k][co]
    transpose_w_kernel<<<C, C>>>(w);

    // 2) Main triangular-group 1x1 conv (GEMM)
    int grid = BATCH * (HW / PX_TILE);  // 4096
    cgconv_kernel<<<grid, THREADS>>>(x, bias, out);
}

// round 2
// speedup vs baseline: 1.8796x; 1.8796x over previous
#include <cuda_runtime.h>
#include <cstdint>

// Problem constants
#define NGROUP 16
#define CPG    8            // channels per group
#define C      128          // total channels
#define HW     (512 * 512)  // pixels per plane
#define BATCH  4
#define PX_TILE 256         // pixels per CTA
#define THREADS 256         // 8 warps; warp w handles groups (15-w) and (w)

typedef unsigned long long u64;

// Transposed weights: g_Wt[k * C + co] = weight[co * C + k]
__device__ float g_Wt[C * C];

__global__ void transpose_w_kernel(const float* __restrict__ w) {
    int co = blockIdx.x;   // 0..127
    int k  = threadIdx.x;  // 0..127
    g_Wt[k * C + co] = w[co * C + k];
}

// ---- packed f32x2 helpers (Blackwell) ----
__device__ __forceinline__ u64 pack2(float v) {
    u64 r;
    unsigned u = __float_as_uint(v);
    asm("mov.b64 %0, {%1, %1};" : "=l"(r) : "r"(u));
    return r;
}
__device__ __forceinline__ void fma2(u64& d, u64 a, u64 b) {
    asm("fma.rn.f32x2 %0, %1, %2, %0;" : "+l"(d) : "l"(a), "l"(b));
}
__device__ __forceinline__ u64 add2(u64 a, u64 b) {
    u64 r;
    asm("add.rn.f32x2 %0, %1, %2;" : "=l"(r) : "l"(a), "l"(b));
    return r;
}

// Compute one output group g for this warp's 8 px/lane slice.
// xlane: &x[base + lane*8]; all loads/stores 16B vectorized.
__device__ __forceinline__ void do_group(
    int g, const float* __restrict__ xlane,
    const float* __restrict__ bias, float* __restrict__ olane)
{
    const int kmax = (g + 1) * CPG;
    const int co0  = g * CPG;

    const float4* wrow = reinterpret_cast<const float4*>(g_Wt) + 2 * g;

    u64 acc[8][4];
#pragma unroll
    for (int j = 0; j < 8; ++j)
#pragma unroll
        for (int q = 0; q < 4; ++q) acc[j][q] = 0ull;

    // distance-1 prefetch of the X row (branch-free clamp keeps reads in-bounds)
    const float* px = xlane;
    ulonglong2 c0 = *reinterpret_cast<const ulonglong2*>(px);
    ulonglong2 c1 = *reinterpret_cast<const ulonglong2*>(px + 4);

    for (int k = 0; k < kmax; ++k) {
        const float* pn = px + ((k + 1 < kmax) ? HW : 0);
        ulonglong2 n0 = *reinterpret_cast<const ulonglong2*>(pn);
        ulonglong2 n1 = *reinterpret_cast<const ulonglong2*>(pn + 4);

        float4 wa = wrow[0];
        float4 wb = wrow[1];
        wrow += C / 4;

        u64 w[8] = { pack2(wa.x), pack2(wa.y), pack2(wa.z), pack2(wa.w),
                     pack2(wb.x), pack2(wb.y), pack2(wb.z), pack2(wb.w) };

#pragma unroll
        for (int j = 0; j < 8; ++j) {
            fma2(acc[j][0], w[j], c0.x);
            fma2(acc[j][1], w[j], c0.y);
            fma2(acc[j][2], w[j], c1.x);
            fma2(acc[j][3], w[j], c1.y);
        }
        c0 = n0; c1 = n1;
        px = pn;
    }

    // Epilogue: bias + store 8 px per output channel
#pragma unroll
    for (int j = 0; j < 8; ++j) {
        u64 bj = pack2(__ldg(bias + co0 + j));
        ulonglong2 v0, v1;
        v0.x = add2(acc[j][0], bj);
        v0.y = add2(acc[j][1], bj);
        v1.x = add2(acc[j][2], bj);
        v1.y = add2(acc[j][3], bj);
        float* orow = olane + (size_t)(co0 + j) * HW;
        reinterpret_cast<ulonglong2*>(orow)[0] = v0;
        reinterpret_cast<ulonglong2*>(orow)[1] = v1;
    }
}

__global__ void __launch_bounds__(THREADS, 2)
cgconv_kernel(const float* __restrict__ x,
              const float* __restrict__ bias,
              float* __restrict__ out)
{
    const int tiles_per_b = HW / PX_TILE;   // 1024
    int tile  = blockIdx.x;                 // 0 .. BATCH*tiles_per_b-1
    int b     = tile / tiles_per_b;
    int t_in  = tile - b * tiles_per_b;
    size_t base = (size_t)b * C * HW + (size_t)t_in * PX_TILE;

    int wid  = threadIdx.x >> 5;            // 0..7
    int lane = threadIdx.x & 31;

    const float* xlane = x   + base + (size_t)lane * 8;
    float*       olane = out + base + (size_t)lane * 8;

    // Two groups per warp: (15-wid) + (wid) -> 136 k-iters for EVERY warp
    do_group(15 - wid, xlane, bias, olane);
    do_group(wid,      xlane, bias, olane);
}

extern "C" void kernel_launch(void* const* d_in, const int* in_sizes, int n_in,
                              void* d_out, int out_size)
{
    const float* x    = (const float*)d_in[0];
    const float* w    = (const float*)d_in[1];
    const float* bias = (const float*)d_in[2];
    float* out        = (float*)d_out;

    transpose_w_kernel<<<C, C>>>(w);

    int grid = BATCH * (HW / PX_TILE);  // 4096
    cgconv_kernel<<<grid, THREADS>>>(x, bias, out);
}